// round 13
// baseline (speedup 1.0000x reference)
#include <cuda_runtime.h>
#include <cuda_bf16.h>
#include <math.h>
#include <stdint.h>

#define BSZ 4
#define SEQ 2048
#define DMODEL 1024
#define NHEADS 8
#define DH 128
#define NEG_INF -1e9f

// ===================== static device scratch =====================
__device__ __nv_bfloat16 g_xhi[BSZ * SEQ * DMODEL];
__device__ __nv_bfloat16 g_xlo[BSZ * SEQ * DMODEL];
__device__ __nv_bfloat16 g_Wqh[NHEADS * DH * DMODEL];
__device__ __nv_bfloat16 g_Wql[NHEADS * DH * DMODEL];
__device__ __nv_bfloat16 g_Wkh[NHEADS * DH * DMODEL];
__device__ __nv_bfloat16 g_Wkl[NHEADS * DH * DMODEL];
__device__ __nv_bfloat16 g_Wvh[NHEADS * DH * DMODEL];
__device__ __nv_bfloat16 g_Wvl[NHEADS * DH * DMODEL];
__device__ __nv_bfloat16 g_Woh[DMODEL * DMODEL];
__device__ __nv_bfloat16 g_Wol[DMODEL * DMODEL];
__device__ __nv_bfloat16 g_Qh[BSZ * NHEADS * SEQ * DH];
__device__ __nv_bfloat16 g_Ql[BSZ * NHEADS * SEQ * DH];
__device__ __nv_bfloat16 g_Kh[BSZ * NHEADS * SEQ * DH];
__device__ __nv_bfloat16 g_Kl[BSZ * NHEADS * SEQ * DH];
__device__ __nv_bfloat16 g_Vh[BSZ * NHEADS * SEQ * DH];
__device__ __nv_bfloat16 g_Vl[BSZ * NHEADS * SEQ * DH];
__device__ float  g_AP[SEQ * SEQ];
__device__ float  g_A[(size_t)BSZ * NHEADS * SEQ * SEQ];
__device__ float2 g_part[(size_t)BSZ * NHEADS * SEQ * 16];
__device__ float2 g_stats[BSZ * NHEADS * SEQ];
__device__ __nv_bfloat16 g_Yh[BSZ * SEQ * DMODEL];
__device__ __nv_bfloat16 g_Yl[BSZ * SEQ * DMODEL];

// ===================== helpers =====================
__device__ __forceinline__ uint32_t smem_u32(const void* p) {
    uint32_t a;
    asm("{ .reg .u64 t; cvta.to.shared.u64 t, %1; cvt.u32.u64 %0, t; }" : "=r"(a) : "l"(p));
    return a;
}
__device__ __forceinline__ void ldsm4(uint32_t* r, uint32_t addr) {
    asm volatile("ldmatrix.sync.aligned.m8n8.x4.shared.b16 {%0,%1,%2,%3}, [%4];"
        : "=r"(r[0]), "=r"(r[1]), "=r"(r[2]), "=r"(r[3]) : "r"(addr));
}
__device__ __forceinline__ void ldsm4_t(uint32_t* r, uint32_t addr) {
    asm volatile("ldmatrix.sync.aligned.m8n8.x4.trans.shared.b16 {%0,%1,%2,%3}, [%4];"
        : "=r"(r[0]), "=r"(r[1]), "=r"(r[2]), "=r"(r[3]) : "r"(addr));
}
__device__ __forceinline__ void mma16816(float* c, const uint32_t* a, uint32_t b0, uint32_t b1) {
    asm volatile("mma.sync.aligned.m16n8k16.row.col.f32.bf16.bf16.f32 "
        "{%0,%1,%2,%3}, {%4,%5,%6,%7}, {%8,%9}, {%0,%1,%2,%3};"
        : "+f"(c[0]), "+f"(c[1]), "+f"(c[2]), "+f"(c[3])
        : "r"(a[0]), "r"(a[1]), "r"(a[2]), "r"(a[3]), "r"(b0), "r"(b1));
}
__device__ __forceinline__ void split4(float4 v, uint2& hi, uint2& lo) {
    __nv_bfloat162 h0 = __floats2bfloat162_rn(v.x, v.y);
    __nv_bfloat162 h1 = __floats2bfloat162_rn(v.z, v.w);
    __nv_bfloat162 l0 = __floats2bfloat162_rn(v.x - __bfloat162float(h0.x),
                                              v.y - __bfloat162float(h0.y));
    __nv_bfloat162 l1 = __floats2bfloat162_rn(v.z - __bfloat162float(h1.x),
                                              v.w - __bfloat162float(h1.y));
    hi.x = *(uint32_t*)&h0; hi.y = *(uint32_t*)&h1;
    lo.x = *(uint32_t*)&l0; lo.y = *(uint32_t*)&l1;
}
__device__ __forceinline__ uint32_t split2(float a, float b, uint32_t& lo) {
    __nv_bfloat162 h = __floats2bfloat162_rn(a, b);
    __nv_bfloat162 l = __floats2bfloat162_rn(a - __bfloat162float(h.x),
                                             b - __bfloat162float(h.y));
    lo = *(uint32_t*)&l;
    return *(uint32_t*)&h;
}
__device__ __forceinline__ void cpa16(uint32_t dst, const void* src) {
    asm volatile("cp.async.cg.shared.global [%0], [%1], 16;" :: "r"(dst), "l"(src) : "memory");
}

// ===================== NT-bf16 cp.async mainloop =====================
// Operands pre-split bf16 hi/lo, row-major [m][ldk]. Tile 128x128, K-chunk 32.
// smem stage: Ahi@0 Alo@10240 Bhi@20480 Blo@30720, rows padded 80B; 2 stages.
#define NT_STAGE 40960
#define NT_SMEM (2 * NT_STAGE)

__device__ __forceinline__ void nt_issue(
    const __nv_bfloat16* Ahi, const __nv_bfloat16* Alo,
    const __nv_bfloat16* Bhi, const __nv_bfloat16* Blo,
    int ldk, int c, uint32_t sstage, int row, int half)
{
    const __nv_bfloat16* g;
    uint32_t d;
    size_t go = (size_t)row * ldk + c * 32 + half * 16;
    uint32_t so = row * 80 + half * 32;
    g = Ahi + go; d = sstage + so;           cpa16(d, g); cpa16(d + 16, g + 8);
    g = Alo + go; d = sstage + 10240 + so;   cpa16(d, g); cpa16(d + 16, g + 8);
    g = Bhi + go; d = sstage + 20480 + so;   cpa16(d, g); cpa16(d + 16, g + 8);
    g = Blo + go; d = sstage + 30720 + so;   cpa16(d, g); cpa16(d + 16, g + 8);
    asm volatile("cp.async.commit_group;" ::: "memory");
}

__device__ __forceinline__ void gemm_nt_bf16(
    const __nv_bfloat16* __restrict__ Ahi, const __nv_bfloat16* __restrict__ Alo,
    const __nv_bfloat16* __restrict__ Bhi, const __nv_bfloat16* __restrict__ Blo,
    int ldk, int K, char* sm, float (&acc)[4][4][4])
{
    const int tid = threadIdx.x, lane = tid & 31, wid = tid >> 5;
    const int morg = (wid >> 2) * 64, norg = (wid & 3) * 32;
    const uint32_t sbase = smem_u32(sm);
    const int row = tid >> 1, half = tid & 1;
    const int nc = K / 32;

    nt_issue(Ahi, Alo, Bhi, Blo, ldk, 0, sbase, row, half);
    nt_issue(Ahi, Alo, Bhi, Blo, ldk, 1, sbase + NT_STAGE, row, half);

    for (int c = 0; c < nc; c++) {
        if (c + 1 < nc) asm volatile("cp.async.wait_group 1;" ::: "memory");
        else            asm volatile("cp.async.wait_group 0;" ::: "memory");
        __syncthreads();
        const uint32_t sst = sbase + (c & 1) * NT_STAGE;
        #pragma unroll
        for (int kh = 0; kh < 2; kh++) {
            uint32_t Ah[4][4], Al[4][4], Bh[2][4], Bl[2][4];
            #pragma unroll
            for (int mf = 0; mf < 4; mf++) {
                uint32_t r = morg + mf * 16 + (lane & 15);
                uint32_t ad = sst + r * 80 + ((lane >> 4) << 4) + kh * 32;
                ldsm4(Ah[mf], ad);
                ldsm4(Al[mf], ad + 10240);
            }
            #pragma unroll
            for (int nb = 0; nb < 2; nb++) {
                uint32_t r = norg + nb * 16 + (lane & 7) + ((lane >> 4) << 3);
                uint32_t ad = sst + 20480 + r * 80 + (((lane >> 3) & 1) << 4) + kh * 32;
                ldsm4(Bh[nb], ad);
                ldsm4(Bl[nb], ad + 10240);
            }
            #pragma unroll
            for (int mf = 0; mf < 4; mf++)
                #pragma unroll
                for (int j = 0; j < 4; j++) {
                    uint32_t b0h = Bh[j >> 1][(j & 1) * 2], b1h = Bh[j >> 1][(j & 1) * 2 + 1];
                    uint32_t b0l = Bl[j >> 1][(j & 1) * 2], b1l = Bl[j >> 1][(j & 1) * 2 + 1];
                    mma16816(acc[mf][j], Ah[mf], b0h, b1h);
                    mma16816(acc[mf][j], Ah[mf], b0l, b1l);
                    mma16816(acc[mf][j], Al[mf], b0h, b1h);
                }
        }
        __syncthreads();
        if (c + 2 < nc)
            nt_issue(Ahi, Alo, Bhi, Blo, ldk, c + 2, sbase + (c & 1) * NT_STAGE, row, half);
    }
}

// ===================== convert: fp32 -> bf16 hi/lo =====================
__global__ void convert_kernel(const float4* __restrict__ in,
                               __nv_bfloat16* __restrict__ hi,
                               __nv_bfloat16* __restrict__ lo, int n4) {
    int i = blockIdx.x * blockDim.x + threadIdx.x;
    if (i >= n4) return;
    float4 v = in[i];
    uint2 h, l;
    split4(v, h, l);
    ((uint2*)hi)[i] = h;
    ((uint2*)lo)[i] = l;
}

// ===================== QKV projection (fused 3-way, bf16 hi/lo out) ==========
__global__ void __launch_bounds__(256, 2) qkv_kernel(
    const __nv_bfloat16* __restrict__ xh, const __nv_bfloat16* __restrict__ xl,
    const __nv_bfloat16* __restrict__ Wqh, const __nv_bfloat16* __restrict__ Wql,
    const __nv_bfloat16* __restrict__ Wkh, const __nv_bfloat16* __restrict__ Wkl,
    const __nv_bfloat16* __restrict__ Wvh, const __nv_bfloat16* __restrict__ Wvl,
    __nv_bfloat16* __restrict__ Qh, __nv_bfloat16* __restrict__ Ql,
    __nv_bfloat16* __restrict__ Kh, __nv_bfloat16* __restrict__ Kl,
    __nv_bfloat16* __restrict__ Vh, __nv_bfloat16* __restrict__ Vl)
{
    extern __shared__ char sm[];
    const __nv_bfloat16* Wh = (blockIdx.z == 0) ? Wqh : (blockIdx.z == 1) ? Wkh : Wvh;
    const __nv_bfloat16* Wl = (blockIdx.z == 0) ? Wql : (blockIdx.z == 1) ? Wkl : Wvl;
    __nv_bfloat16* Oh = (blockIdx.z == 0) ? Qh : (blockIdx.z == 1) ? Kh : Vh;
    __nv_bfloat16* Ol = (blockIdx.z == 0) ? Ql : (blockIdx.z == 1) ? Kl : Vl;

    float acc[4][4][4] = {};
    const int tileM = blockIdx.y * 128, tileN = blockIdx.x * 128;
    gemm_nt_bf16(xh + (size_t)tileM * DMODEL, xl + (size_t)tileM * DMODEL,
                 Wh + (size_t)tileN * DMODEL, Wl + (size_t)tileN * DMODEL,
                 DMODEL, DMODEL, sm, acc);

    const int lane = threadIdx.x & 31, wid = threadIdx.x >> 5;
    const int h = blockIdx.x;
    #pragma unroll
    for (int mf = 0; mf < 4; mf++) {
        int row = tileM + (wid >> 2) * 64 + mf * 16 + (lane >> 2);
        int r1 = row + 8;
        #pragma unroll
        for (int j = 0; j < 4; j++) {
            int e = (wid & 3) * 32 + j * 8 + (lane & 3) * 2;
            int b0 = row >> 11, ns0 = row & 2047;
            size_t base0 = (((size_t)(b0 * NHEADS + h) * SEQ + ns0) * DH + e);
            uint32_t lo0;
            uint32_t hi0 = split2(acc[mf][j][0], acc[mf][j][1], lo0);
            *(uint32_t*)(Oh + base0) = hi0;
            *(uint32_t*)(Ol + base0) = lo0;
            int b1 = r1 >> 11, ns1 = r1 & 2047;
            size_t base1 = (((size_t)(b1 * NHEADS + h) * SEQ + ns1) * DH + e);
            uint32_t lo1;
            uint32_t hi1 = split2(acc[mf][j][2], acc[mf][j][3], lo1);
            *(uint32_t*)(Oh + base1) = hi1;
            *(uint32_t*)(Ol + base1) = lo1;
        }
    }
}

// ===================== scores + partial row stats =====================
__global__ void __launch_bounds__(256, 2) scores_kernel(
    const __nv_bfloat16* __restrict__ Qh, const __nv_bfloat16* __restrict__ Ql,
    const __nv_bfloat16* __restrict__ Kh, const __nv_bfloat16* __restrict__ Kl,
    const int* __restrict__ mask, const float* __restrict__ AP,
    float* __restrict__ Abuf, float2* __restrict__ part)
{
    extern __shared__ char sm[];
    float acc[4][4][4] = {};
    const int bh = blockIdx.z;
    const int b = bh >> 3;
    const size_t hb = (size_t)bh * SEQ * DH;
    const int tileM = blockIdx.y * 128, tileN = blockIdx.x * 128;
    gemm_nt_bf16(Qh + hb + (size_t)tileM * DH, Ql + hb + (size_t)tileM * DH,
                 Kh + hb + (size_t)tileN * DH, Kl + hb + (size_t)tileN * DH,
                 DH, DH, sm, acc);

    float* C = Abuf + (size_t)bh * SEQ * SEQ;
    const int tid = threadIdx.x, lane = tid & 31, wid = tid >> 5;
    const int morg = (wid >> 2) * 64, norg = (wid & 3) * 32;
    const int* mb = mask + b * SEQ;
    float2* smst = (float2*)sm;   // dead NT stage

    #pragma unroll
    for (int mf = 0; mf < 4; mf++) {
        int rl0 = morg + mf * 16 + (lane >> 2);
        int rl1 = rl0 + 8;
        int r0 = tileM + rl0, r1 = tileM + rl1;
        int mr0 = mb[r0], mr1 = mb[r1];
        float tm0 = -1e38f, ts0 = 0.f, tm1 = -1e38f, ts1 = 0.f;
        #pragma unroll
        for (int j = 0; j < 4; j++) {
            int col = tileN + norg + j * 8 + (lane & 3) * 2;
            int mc0 = mb[col], mc1 = mb[col + 1];
            const float* ap0 = AP + (size_t)r0 * SEQ + col;
            const float* ap1 = AP + (size_t)r1 * SEQ + col;
            float2 o0, o1;
            o0.x = (mr0 && mc0) ? acc[mf][j][0] + ap0[0] : NEG_INF;
            o0.y = (mr0 && mc1) ? acc[mf][j][1] + ap0[1] : NEG_INF;
            o1.x = (mr1 && mc0) ? acc[mf][j][2] + ap1[0] : NEG_INF;
            o1.y = (mr1 && mc1) ? acc[mf][j][3] + ap1[1] : NEG_INF;
            *(float2*)(C + (size_t)r0 * SEQ + col) = o0;
            *(float2*)(C + (size_t)r1 * SEQ + col) = o1;
            float mx0 = fmaxf(tm0, fmaxf(o0.x, o0.y));
            ts0 = ts0 * __expf(tm0 - mx0) + __expf(o0.x - mx0) + __expf(o0.y - mx0);
            tm0 = mx0;
            float mx1 = fmaxf(tm1, fmaxf(o1.x, o1.y));
            ts1 = ts1 * __expf(tm1 - mx1) + __expf(o1.x - mx1) + __expf(o1.y - mx1);
            tm1 = mx1;
        }
        #pragma unroll
        for (int dx = 1; dx <= 2; dx <<= 1) {
            float om = __shfl_xor_sync(0xffffffff, tm0, dx);
            float os = __shfl_xor_sync(0xffffffff, ts0, dx);
            float M = fmaxf(tm0, om);
            ts0 = ts0 * __expf(tm0 - M) + os * __expf(om - M);
            tm0 = M;
            om = __shfl_xor_sync(0xffffffff, tm1, dx);
            os = __shfl_xor_sync(0xffffffff, ts1, dx);
            M = fmaxf(tm1, om);
            ts1 = ts1 * __expf(tm1 - M) + os * __expf(om - M);
            tm1 = M;
        }
        if ((lane & 3) == 0) {
            int base = wid * 64 + mf * 16 + (lane >> 2);
            smst[base]     = make_float2(tm0, ts0);
            smst[base + 8] = make_float2(tm1, ts1);
        }
    }
    __syncthreads();
    if (tid < 128) {
        int grp = tid >> 6;
        int rl = tid & 63;
        float M = -1e38f, S = 0.f;
        #pragma unroll
        for (int w = 0; w < 4; w++) {
            float2 p = smst[(grp * 4 + w) * 64 + rl];
            float Mn = fmaxf(M, p.x);
            S = S * __expf(M - Mn) + p.y * __expf(p.x - Mn);
            M = Mn;
        }
        part[((size_t)bh * SEQ + tileM + grp * 64 + rl) * 16 + blockIdx.x] = make_float2(M, S);
    }
}

// ===================== merge partial stats =====================
__global__ void __launch_bounds__(256) statsmerge_kernel(
    const float2* __restrict__ part, float2* __restrict__ stats)
{
    int row = blockIdx.x * blockDim.x + threadIdx.x;
    if (row >= BSZ * NHEADS * SEQ) return;
    const float2* p = part + (size_t)row * 16;
    float M = -1e38f, S = 0.f;
    #pragma unroll
    for (int t = 0; t < 16; t++) {
        float2 q = p[t];
        float Mn = fmaxf(M, q.x);
        S = S * __expf(M - Mn) + q.y * __expf(q.x - Mn);
        M = Mn;
    }
    stats[row] = make_float2(M, S);
}

// ===================== av: y = A^T V, softmax at load, bf16 hi/lo Y out ==========
#define TT_STAGE 34816
#define TT_SMEM (2 * TT_STAGE)

__device__ __forceinline__ float4 exp_norm4(float4 v, float mx, float inv) {
    v.x = __expf(v.x - mx) * inv;
    v.y = __expf(v.y - mx) * inv;
    v.z = __expf(v.z - mx) * inv;
    v.w = __expf(v.w - mx) * inv;
    return v;
}

__global__ void __launch_bounds__(256, 2) av_kernel(
    const __nv_bfloat16* __restrict__ Vh, const __nv_bfloat16* __restrict__ Vl,
    const float* __restrict__ Abuf, const float2* __restrict__ stats,
    float* __restrict__ attOut, int hasAtt,
    __nv_bfloat16* __restrict__ Yh, __nv_bfloat16* __restrict__ Yl)
{
    extern __shared__ char sm[];
    float acc[4][4][4] = {};
    const int bh = blockIdx.y;
    const int b = bh >> 3, h = bh & 7;
    const int tileM = blockIdx.x * 128;
    const float* Ag = Abuf + (size_t)bh * SEQ * SEQ + tileM;
    const __nv_bfloat16* Vbh = Vh + (size_t)bh * SEQ * DH;
    const __nv_bfloat16* Vbl = Vl + (size_t)bh * SEQ * DH;
    const float2* strow = stats + (size_t)bh * SEQ;
    float* attB = attOut + (size_t)b * SEQ * SEQ + tileM;
    const bool wAtt = (h == 7) && hasAtt;

    const int tid = threadIdx.x, lane = tid & 31, wid = tid >> 5;
    const int morg = (wid >> 2) * 64, norg = (wid & 3) * 32;
    const int kr = tid >> 5, cg = tid & 31;
    const uint32_t sbase = smem_u32(sm);
    const int nc = SEQ / 32;
    float4 va[4];
    uint2 vbh[4], vbl[4];

    #pragma unroll
    for (int rb = 0; rb < 4; rb++) {
        int j = kr + rb * 8;
        float2 st = strow[j];
        float inv = 1.0f / st.y;
        float4 v = *(const float4*)(Ag + (size_t)j * SEQ + cg * 4);
        v = exp_norm4(v, st.x, inv);
        if (wAtt) *(float4*)(attB + (size_t)j * SEQ + cg * 4) = v;
        va[rb] = v;
        vbh[rb] = *(const uint2*)(Vbh + (size_t)j * DH + cg * 4);
        vbl[rb] = *(const uint2*)(Vbl + (size_t)j * DH + cg * 4);
    }
    {
        char* st = sm;
        #pragma unroll
        for (int rb = 0; rb < 4; rb++) {
            uint2 hi, lo;
            int off = (kr + rb * 8) * 272 + cg * 8;
            split4(va[rb], hi, lo);
            *(uint2*)(st + off) = hi; *(uint2*)(st + 8704 + off) = lo;
            *(uint2*)(st + 17408 + off) = vbh[rb];
            *(uint2*)(st + 26112 + off) = vbl[rb];
        }
    }

    for (int c = 0; c < nc; c++) {
        __syncthreads();
        if (c + 1 < nc) {
            #pragma unroll
            for (int rb = 0; rb < 4; rb++) {
                int j = (c + 1) * 32 + kr + rb * 8;
                float2 st = strow[j];
                float inv = 1.0f / st.y;
                float4 v = *(const float4*)(Ag + (size_t)j * SEQ + cg * 4);
                v = exp_norm4(v, st.x, inv);
                if (wAtt) *(float4*)(attB + (size_t)j * SEQ + cg * 4) = v;
                va[rb] = v;
                vbh[rb] = *(const uint2*)(Vbh + (size_t)j * DH + cg * 4);
                vbl[rb] = *(const uint2*)(Vbl + (size_t)j * DH + cg * 4);
            }
        }
        const uint32_t sst = sbase + (c & 1) * TT_STAGE;
        #pragma unroll
        for (int kh = 0; kh < 2; kh++) {
            uint32_t Ah[4][4], Al[4][4], Bh[2][4], Bl[2][4];
            #pragma unroll
            for (int mf = 0; mf < 4; mf++) {
                uint32_t krow = (lane & 7) + ((lane >> 4) << 3) + kh * 16;
                uint32_t ad = sst + krow * 272 + (((lane >> 3) & 1) << 4) + (morg + mf * 16) * 2;
                ldsm4_t(Ah[mf], ad);
                ldsm4_t(Al[mf], ad + 8704);
            }
            #pragma unroll
            for (int nb = 0; nb < 2; nb++) {
                uint32_t krow = (lane & 7) + (((lane >> 3) & 1) << 3) + kh * 16;
                uint32_t ad = sst + 17408 + krow * 272 + ((lane >> 4) << 4) + (norg + nb * 16) * 2;
                ldsm4_t(Bh[nb], ad);
                ldsm4_t(Bl[nb], ad + 8704);
            }
            #pragma unroll
            for (int mf = 0; mf < 4; mf++)
                #pragma unroll
                for (int j = 0; j < 4; j++) {
                    uint32_t b0h = Bh[j >> 1][(j & 1) * 2], b1h = Bh[j >> 1][(j & 1) * 2 + 1];
                    uint32_t b0l = Bl[j >> 1][(j & 1) * 2], b1l = Bl[j >> 1][(j & 1) * 2 + 1];
                    mma16816(acc[mf][j], Ah[mf], b0h, b1h);
                    mma16816(acc[mf][j], Ah[mf], b0l, b1l);
                    mma16816(acc[mf][j], Al[mf], b0h, b1h);
                }
        }
        __syncthreads();
        if (c + 1 < nc) {
            char* st = sm + ((c + 1) & 1) * TT_STAGE;
            #pragma unroll
            for (int rb = 0; rb < 4; rb++) {
                uint2 hi, lo;
                int off = (kr + rb * 8) * 272 + cg * 8;
                split4(va[rb], hi, lo);
                *(uint2*)(st + off) = hi; *(uint2*)(st + 8704 + off) = lo;
                *(uint2*)(st + 17408 + off) = vbh[rb];
                *(uint2*)(st + 26112 + off) = vbl[rb];
            }
        }
    }

    #pragma unroll
    for (int mf = 0; mf < 4; mf++) {
        int i0 = tileM + (wid >> 2) * 64 + mf * 16 + (lane >> 2);
        #pragma unroll
        for (int j = 0; j < 4; j++) {
            int e = (wid & 3) * 32 + j * 8 + (lane & 3) * 2;
            size_t base0 = ((size_t)b * SEQ + i0) * DMODEL + h * DH + e;
            size_t base1 = ((size_t)b * SEQ + i0 + 8) * DMODEL + h * DH + e;
            uint32_t lo0;
            uint32_t hi0 = split2(acc[mf][j][0], acc[mf][j][1], lo0);
            *(uint32_t*)(Yh + base0) = hi0;
            *(uint32_t*)(Yl + base0) = lo0;
            uint32_t lo1;
            uint32_t hi1 = split2(acc[mf][j][2], acc[mf][j][3], lo1);
            *(uint32_t*)(Yh + base1) = hi1;
            *(uint32_t*)(Yl + base1) = lo1;
        }
    }
}

// ===================== out = Y * Wout^T =====================
__global__ void __launch_bounds__(256, 2) outproj_kernel(
    const __nv_bfloat16* __restrict__ Yh, const __nv_bfloat16* __restrict__ Yl,
    const __nv_bfloat16* __restrict__ Wh, const __nv_bfloat16* __restrict__ Wl,
    float* __restrict__ out)
{
    extern __shared__ char sm[];
    float acc[4][4][4] = {};
    const int tileM = blockIdx.y * 128, tileN = blockIdx.x * 128;
    gemm_nt_bf16(Yh + (size_t)tileM * DMODEL, Yl + (size_t)tileM * DMODEL,
                 Wh + (size_t)tileN * DMODEL, Wl + (size_t)tileN * DMODEL,
                 DMODEL, DMODEL, sm, acc);

    const int lane = threadIdx.x & 31, wid = threadIdx.x >> 5;
    #pragma unroll
    for (int mf = 0; mf < 4; mf++) {
        int row = tileM + (wid >> 2) * 64 + mf * 16 + (lane >> 2);
        #pragma unroll
        for (int j = 0; j < 4; j++) {
            int col = tileN + (wid & 3) * 32 + j * 8 + (lane & 3) * 2;
            *(float2*)(out + (size_t)row * DMODEL + col) =
                make_float2(acc[mf][j][0], acc[mf][j][1]);
            *(float2*)(out + (size_t)(row + 8) * DMODEL + col) =
                make_float2(acc[mf][j][2], acc[mf][j][3]);
        }
    }
}

// ===================== AP table =====================
__global__ void ap_kernel(float* __restrict__ AP) {
    int idx = blockIdx.x * blockDim.x + threadIdx.x;
    const int total = SEQ * (SEQ / 2);
    if (idx >= total) return;
    int p = idx / (SEQ / 2);
    int i = idx % (SEQ / 2);
    float denom = powf(10000.0f, (2.0f * (float)i) / 1024.0f);
    float angle = (float)p / denom;
    float s, c;
    sincosf(angle, &s, &c);
    AP[(size_t)p * SEQ + 2 * i]     = s;
    AP[(size_t)p * SEQ + 2 * i + 1] = c;
}

// ===================== launch =====================
extern "C" void kernel_launch(void* const* d_in, const int* in_sizes, int n_in,
                              void* d_out, int out_size) {
    const float* x    = (const float*)d_in[0];
    const int*   mask = (const int*)  d_in[1];
    const float* Wq   = (const float*)d_in[2];
    const float* Wk   = (const float*)d_in[3];
    const float* Wv   = (const float*)d_in[4];
    const float* Wout = (const float*)d_in[5];
    float* out = (float*)d_out;

    const long long outElems = (long long)BSZ * SEQ * DMODEL;
    const long long attElems = (long long)BSZ * SEQ * SEQ;
    int hasAtt = ((long long)out_size >= outElems + attElems) ? 1 : 0;
    float* attOut = out + outElems;

    __nv_bfloat16 *xh, *xl, *wqh, *wql, *wkh, *wkl, *wvh, *wvl, *woh, *wol;
    __nv_bfloat16 *qh, *ql, *kh, *kl, *vh, *vl, *yh, *yl;
    float *APp, *Ap;
    float2 *Sp, *Pp;
    cudaGetSymbolAddress((void**)&xh, g_xhi);  cudaGetSymbolAddress((void**)&xl, g_xlo);
    cudaGetSymbolAddress((void**)&wqh, g_Wqh); cudaGetSymbolAddress((void**)&wql, g_Wql);
    cudaGetSymbolAddress((void**)&wkh, g_Wkh); cudaGetSymbolAddress((void**)&wkl, g_Wkl);
    cudaGetSymbolAddress((void**)&wvh, g_Wvh); cudaGetSymbolAddress((void**)&wvl, g_Wvl);
    cudaGetSymbolAddress((void**)&woh, g_Woh); cudaGetSymbolAddress((void**)&wol, g_Wol);
    cudaGetSymbolAddress((void**)&qh, g_Qh);   cudaGetSymbolAddress((void**)&ql, g_Ql);
    cudaGetSymbolAddress((void**)&kh, g_Kh);   cudaGetSymbolAddress((void**)&kl, g_Kl);
    cudaGetSymbolAddress((void**)&vh, g_Vh);   cudaGetSymbolAddress((void**)&vl, g_Vl);
    cudaGetSymbolAddress((void**)&yh, g_Yh);   cudaGetSymbolAddress((void**)&yl, g_Yl);
    cudaGetSymbolAddress((void**)&APp, g_AP);
    cudaGetSymbolAddress((void**)&Ap, g_A);
    cudaGetSymbolAddress((void**)&Sp, g_stats);
    cudaGetSymbolAddress((void**)&Pp, g_part);

    cudaFuncSetAttribute(qkv_kernel,     cudaFuncAttributeMaxDynamicSharedMemorySize, NT_SMEM);
    cudaFuncSetAttribute(scores_kernel,  cudaFuncAttributeMaxDynamicSharedMemorySize, NT_SMEM);
    cudaFuncSetAttribute(outproj_kernel, cudaFuncAttributeMaxDynamicSharedMemorySize, NT_SMEM);
    cudaFuncSetAttribute(av_kernel,      cudaFuncAttributeMaxDynamicSharedMemorySize, TT_SMEM);

    // 1. AP table + conversions
    {
        int total = SEQ * (SEQ / 2);
        ap_kernel<<<(total + 255) / 256, 256>>>(APp);
        int n4 = (BSZ * SEQ * DMODEL) / 4;
        convert_kernel<<<(n4 + 255) / 256, 256>>>((const float4*)x, xh, xl, n4);
        int w4 = (NHEADS * DH * DMODEL) / 4;
        convert_kernel<<<(w4 + 255) / 256, 256>>>((const float4*)Wq, wqh, wql, w4);
        convert_kernel<<<(w4 + 255) / 256, 256>>>((const float4*)Wk, wkh, wkl, w4);
        convert_kernel<<<(w4 + 255) / 256, 256>>>((const float4*)Wv, wvh, wvl, w4);
        int o4 = (DMODEL * DMODEL) / 4;
        convert_kernel<<<(o4 + 255) / 256, 256>>>((const float4*)Wout, woh, wol, o4);
    }
    // 2. QKV projections (one launch)
    {
        dim3 g(DMODEL / 128, (BSZ * SEQ) / 128, 3);
        qkv_kernel<<<g, 256, NT_SMEM>>>(xh, xl, wqh, wql, wkh, wkl, wvh, wvl,
                                        qh, ql, kh, kl, vh, vl);
    }
    // 3. scores -> g_A + per-tile row stats
    {
        dim3 g(SEQ / 128, SEQ / 128, BSZ * NHEADS);
        scores_kernel<<<g, 256, NT_SMEM>>>(qh, ql, kh, kl, mask, APp, Ap, Pp);
    }
    // 4. merge partial stats
    statsmerge_kernel<<<(BSZ * NHEADS * SEQ + 255) / 256, 256>>>(Pp, Sp);
    // 5. y = A^T V with softmax at load (+ attOut for h==7)
    {
        dim3 g(SEQ / 128, BSZ * NHEADS);
        av_kernel<<<g, 256, TT_SMEM>>>(vh, vl, Ap, Sp, attOut, hasAtt, yh, yl);
    }
    // 6. out projection
    {
        dim3 g(DMODEL / 128, (BSZ * SEQ) / 128);
        outproj_kernel<<<g, 256, NT_SMEM>>>(yh, yl, woh, wol, out);
    }
}

// round 15
// speedup vs baseline: 1.5895x; 1.5895x over previous
#include <cuda_runtime.h>
#include <cuda_bf16.h>
#include <math.h>
#include <stdint.h>

#define BSZ 4
#define SEQ 2048
#define DMODEL 1024
#define NHEADS 8
#define DH 128
#define NEG_INF -1e9f

// ===================== static device scratch =====================
__device__ float  g_Q[BSZ * NHEADS * SEQ * DH];
__device__ float  g_K[BSZ * NHEADS * SEQ * DH];
__device__ float  g_V[BSZ * NHEADS * SEQ * DH];
__device__ float  g_AP[SEQ * SEQ];
__device__ float  g_A[(size_t)BSZ * NHEADS * SEQ * SEQ];
__device__ float2 g_part[(size_t)BSZ * NHEADS * SEQ * 16];
__device__ float2 g_stats[BSZ * NHEADS * SEQ];
__device__ float  g_Y[BSZ * SEQ * DMODEL];

// ===================== helpers =====================
__device__ __forceinline__ uint32_t smem_u32(const void* p) {
    uint32_t a;
    asm("{ .reg .u64 t; cvta.to.shared.u64 t, %1; cvt.u32.u64 %0, t; }" : "=r"(a) : "l"(p));
    return a;
}
__device__ __forceinline__ void ldsm4(uint32_t* r, uint32_t addr) {
    asm volatile("ldmatrix.sync.aligned.m8n8.x4.shared.b16 {%0,%1,%2,%3}, [%4];"
        : "=r"(r[0]), "=r"(r[1]), "=r"(r[2]), "=r"(r[3]) : "r"(addr));
}
__device__ __forceinline__ void ldsm4_t(uint32_t* r, uint32_t addr) {
    asm volatile("ldmatrix.sync.aligned.m8n8.x4.trans.shared.b16 {%0,%1,%2,%3}, [%4];"
        : "=r"(r[0]), "=r"(r[1]), "=r"(r[2]), "=r"(r[3]) : "r"(addr));
}
__device__ __forceinline__ void mma16816(float* c, const uint32_t* a, uint32_t b0, uint32_t b1) {
    asm volatile("mma.sync.aligned.m16n8k16.row.col.f32.bf16.bf16.f32 "
        "{%0,%1,%2,%3}, {%4,%5,%6,%7}, {%8,%9}, {%0,%1,%2,%3};"
        : "+f"(c[0]), "+f"(c[1]), "+f"(c[2]), "+f"(c[3])
        : "r"(a[0]), "r"(a[1]), "r"(a[2]), "r"(a[3]), "r"(b0), "r"(b1));
}
__device__ __forceinline__ void split4(float4 v, uint2& hi, uint2& lo) {
    __nv_bfloat162 h0 = __floats2bfloat162_rn(v.x, v.y);
    __nv_bfloat162 h1 = __floats2bfloat162_rn(v.z, v.w);
    __nv_bfloat162 l0 = __floats2bfloat162_rn(v.x - __bfloat162float(h0.x),
                                              v.y - __bfloat162float(h0.y));
    __nv_bfloat162 l1 = __floats2bfloat162_rn(v.z - __bfloat162float(h1.x),
                                              v.w - __bfloat162float(h1.y));
    hi.x = *(uint32_t*)&h0; hi.y = *(uint32_t*)&h1;
    lo.x = *(uint32_t*)&l0; lo.y = *(uint32_t*)&l1;
}

// ===================== NT mainloop, 256 threads (scores) =====================
#define NT_STAGE 40960
#define NT_SMEM (2 * NT_STAGE)

__device__ __forceinline__ void gemm_nt_mma(
    const float* __restrict__ Ag, int lda,
    const float* __restrict__ Bg, int ldb,
    int K, char* sm, float (&acc)[4][4][4])
{
    const int tid = threadIdx.x, lane = tid & 31, wid = tid >> 5;
    const int morg = (wid >> 2) * 64, norg = (wid & 3) * 32;
    const int lr = tid >> 3, lc = (tid & 7) << 2;
    const uint32_t sbase = smem_u32(sm);
    const int nc = K / 32;
    float4 va[4], vb[4];

    #pragma unroll
    for (int rb = 0; rb < 4; rb++) {
        va[rb] = *(const float4*)(Ag + (size_t)(lr + rb * 32) * lda + lc);
        vb[rb] = *(const float4*)(Bg + (size_t)(lr + rb * 32) * ldb + lc);
    }
    {
        char* st = sm;
        #pragma unroll
        for (int rb = 0; rb < 4; rb++) {
            uint2 hi, lo;
            int off = (lr + rb * 32) * 80 + lc * 2;
            split4(va[rb], hi, lo);
            *(uint2*)(st + off) = hi; *(uint2*)(st + 10240 + off) = lo;
            split4(vb[rb], hi, lo);
            *(uint2*)(st + 20480 + off) = hi; *(uint2*)(st + 30720 + off) = lo;
        }
    }

    for (int c = 0; c < nc; c++) {
        __syncthreads();
        if (c + 1 < nc) {
            #pragma unroll
            for (int rb = 0; rb < 4; rb++) {
                va[rb] = *(const float4*)(Ag + (size_t)(lr + rb * 32) * lda + (c + 1) * 32 + lc);
                vb[rb] = *(const float4*)(Bg + (size_t)(lr + rb * 32) * ldb + (c + 1) * 32 + lc);
            }
        }
        const uint32_t sst = sbase + (c & 1) * NT_STAGE;
        #pragma unroll
        for (int kh = 0; kh < 2; kh++) {
            uint32_t Ah[4][4], Al[4][4], Bh[2][4], Bl[2][4];
            #pragma unroll
            for (int mf = 0; mf < 4; mf++) {
                uint32_t r = morg + mf * 16 + (lane & 15);
                uint32_t ad = sst + r * 80 + ((lane >> 4) << 4) + kh * 32;
                ldsm4(Ah[mf], ad);
                ldsm4(Al[mf], ad + 10240);
            }
            #pragma unroll
            for (int nb = 0; nb < 2; nb++) {
                uint32_t r = norg + nb * 16 + (lane & 7) + ((lane >> 4) << 3);
                uint32_t ad = sst + 20480 + r * 80 + (((lane >> 3) & 1) << 4) + kh * 32;
                ldsm4(Bh[nb], ad);
                ldsm4(Bl[nb], ad + 10240);
            }
            #pragma unroll
            for (int mf = 0; mf < 4; mf++)
                #pragma unroll
                for (int j = 0; j < 4; j++) {
                    uint32_t b0h = Bh[j >> 1][(j & 1) * 2], b1h = Bh[j >> 1][(j & 1) * 2 + 1];
                    uint32_t b0l = Bl[j >> 1][(j & 1) * 2], b1l = Bl[j >> 1][(j & 1) * 2 + 1];
                    mma16816(acc[mf][j], Ah[mf], b0h, b1h);
                    mma16816(acc[mf][j], Ah[mf], b0l, b1l);
                    mma16816(acc[mf][j], Al[mf], b0h, b1h);
                }
        }
        __syncthreads();
        if (c + 1 < nc) {
            char* st = sm + ((c + 1) & 1) * NT_STAGE;
            #pragma unroll
            for (int rb = 0; rb < 4; rb++) {
                uint2 hi, lo;
                int off = (lr + rb * 32) * 80 + lc * 2;
                split4(va[rb], hi, lo);
                *(uint2*)(st + off) = hi; *(uint2*)(st + 10240 + off) = lo;
                split4(vb[rb], hi, lo);
                *(uint2*)(st + 20480 + off) = hi; *(uint2*)(st + 30720 + off) = lo;
            }
        }
    }
}

// ===================== NT mainloop, 512 threads, 256x128 tile (qkv/outproj) ==========
// smem: Ahi@0 (256x80) Alo@20480 Bhi@40960 (128x80) Blo@51200; stage 61440; x2
#define NT5_STAGE 61440
#define NT5_SMEM (2 * NT5_STAGE)

__device__ __forceinline__ void gemm_nt_mma_512(
    const float* __restrict__ Ag, int lda,
    const float* __restrict__ Bg, int ldb,
    int K, char* sm, float (&acc)[4][4][4])
{
    const int tid = threadIdx.x, lane = tid & 31, wid = tid >> 5;   // wid 0..15
    const int morg = (wid >> 2) * 64, norg = (wid & 3) * 32;        // morg 0..192
    const int ar = tid >> 3, ac = (tid & 7) << 2;                   // ar 0..63
    const uint32_t sbase = smem_u32(sm);
    const int nc = K / 32;
    float4 va[4], vb[2];

    #pragma unroll
    for (int rb = 0; rb < 4; rb++)
        va[rb] = *(const float4*)(Ag + (size_t)(ar + rb * 64) * lda + ac);
    #pragma unroll
    for (int rb = 0; rb < 2; rb++)
        vb[rb] = *(const float4*)(Bg + (size_t)(ar + rb * 64) * ldb + ac);
    {
        char* st = sm;
        #pragma unroll
        for (int rb = 0; rb < 4; rb++) {
            uint2 hi, lo;
            int off = (ar + rb * 64) * 80 + ac * 2;
            split4(va[rb], hi, lo);
            *(uint2*)(st + off) = hi; *(uint2*)(st + 20480 + off) = lo;
        }
        #pragma unroll
        for (int rb = 0; rb < 2; rb++) {
            uint2 hi, lo;
            int off = (ar + rb * 64) * 80 + ac * 2;
            split4(vb[rb], hi, lo);
            *(uint2*)(st + 40960 + off) = hi; *(uint2*)(st + 51200 + off) = lo;
        }
    }

    for (int c = 0; c < nc; c++) {
        __syncthreads();
        if (c + 1 < nc) {
            #pragma unroll
            for (int rb = 0; rb < 4; rb++)
                va[rb] = *(const float4*)(Ag + (size_t)(ar + rb * 64) * lda + (c + 1) * 32 + ac);
            #pragma unroll
            for (int rb = 0; rb < 2; rb++)
                vb[rb] = *(const float4*)(Bg + (size_t)(ar + rb * 64) * ldb + (c + 1) * 32 + ac);
        }
        const uint32_t sst = sbase + (c & 1) * NT5_STAGE;
        #pragma unroll
        for (int kh = 0; kh < 2; kh++) {
            uint32_t Ah[4][4], Al[4][4], Bh[2][4], Bl[2][4];
            #pragma unroll
            for (int mf = 0; mf < 4; mf++) {
                uint32_t r = morg + mf * 16 + (lane & 15);
                uint32_t ad = sst + r * 80 + ((lane >> 4) << 4) + kh * 32;
                ldsm4(Ah[mf], ad);
                ldsm4(Al[mf], ad + 20480);
            }
            #pragma unroll
            for (int nb = 0; nb < 2; nb++) {
                uint32_t r = norg + nb * 16 + (lane & 7) + ((lane >> 4) << 3);
                uint32_t ad = sst + 40960 + r * 80 + (((lane >> 3) & 1) << 4) + kh * 32;
                ldsm4(Bh[nb], ad);
                ldsm4(Bl[nb], ad + 10240);
            }
            #pragma unroll
            for (int mf = 0; mf < 4; mf++)
                #pragma unroll
                for (int j = 0; j < 4; j++) {
                    uint32_t b0h = Bh[j >> 1][(j & 1) * 2], b1h = Bh[j >> 1][(j & 1) * 2 + 1];
                    uint32_t b0l = Bl[j >> 1][(j & 1) * 2], b1l = Bl[j >> 1][(j & 1) * 2 + 1];
                    mma16816(acc[mf][j], Ah[mf], b0h, b1h);
                    mma16816(acc[mf][j], Ah[mf], b0l, b1l);
                    mma16816(acc[mf][j], Al[mf], b0h, b1h);
                }
        }
        __syncthreads();
        if (c + 1 < nc) {
            char* st = sm + ((c + 1) & 1) * NT5_STAGE;
            #pragma unroll
            for (int rb = 0; rb < 4; rb++) {
                uint2 hi, lo;
                int off = (ar + rb * 64) * 80 + ac * 2;
                split4(va[rb], hi, lo);
                *(uint2*)(st + off) = hi; *(uint2*)(st + 20480 + off) = lo;
            }
            #pragma unroll
            for (int rb = 0; rb < 2; rb++) {
                uint2 hi, lo;
                int off = (ar + rb * 64) * 80 + ac * 2;
                split4(vb[rb], hi, lo);
                *(uint2*)(st + 40960 + off) = hi; *(uint2*)(st + 51200 + off) = lo;
            }
        }
    }
}

// ===================== QKV projection (512 thr, 256x128 tile, fused 3-way) ==========
__global__ void __launch_bounds__(512, 1) qkv_kernel(
    const float* __restrict__ x,
    const float* __restrict__ Wq, const float* __restrict__ Wk, const float* __restrict__ Wv,
    float* __restrict__ Qp, float* __restrict__ Kp, float* __restrict__ Vp)
{
    extern __shared__ char sm[];
    const float* W = (blockIdx.z == 0) ? Wq : (blockIdx.z == 1) ? Wk : Wv;
    float* outp    = (blockIdx.z == 0) ? Qp : (blockIdx.z == 1) ? Kp : Vp;

    float acc[4][4][4] = {};
    const int tileM = blockIdx.y * 256, tileN = blockIdx.x * 128;
    gemm_nt_mma_512(x + (size_t)tileM * DMODEL, DMODEL,
                    W + (size_t)tileN * DMODEL, DMODEL, DMODEL, sm, acc);

    const int lane = threadIdx.x & 31, wid = threadIdx.x >> 5;
    const int h = blockIdx.x;
    #pragma unroll
    for (int mf = 0; mf < 4; mf++) {
        int row = tileM + (wid >> 2) * 64 + mf * 16 + (lane >> 2);
        #pragma unroll
        for (int j = 0; j < 4; j++) {
            int e = (wid & 3) * 32 + j * 8 + (lane & 3) * 2;
            int b0 = row >> 11, ns0 = row & 2047;
            float* d0 = outp + (((size_t)(b0 * NHEADS + h) * SEQ + ns0) * DH + e);
            *(float2*)d0 = make_float2(acc[mf][j][0], acc[mf][j][1]);
            int r1 = row + 8;
            int b1 = r1 >> 11, ns1 = r1 & 2047;
            float* d1 = outp + (((size_t)(b1 * NHEADS + h) * SEQ + ns1) * DH + e);
            *(float2*)d1 = make_float2(acc[mf][j][2], acc[mf][j][3]);
        }
    }
}

// ===================== scores + partial row stats =====================
__global__ void __launch_bounds__(256, 2) scores_kernel(
    const float* __restrict__ Q, const float* __restrict__ Km,
    const int* __restrict__ mask, const float* __restrict__ AP,
    float* __restrict__ Abuf, float2* __restrict__ part)
{
    extern __shared__ char sm[];
    float acc[4][4][4] = {};
    const int bh = blockIdx.z;
    const int b = bh >> 3;
    const size_t hb = (size_t)bh * SEQ * DH;
    const int tileM = blockIdx.y * 128, tileN = blockIdx.x * 128;
    gemm_nt_mma(Q + hb + (size_t)tileM * DH, DH,
                Km + hb + (size_t)tileN * DH, DH, DH, sm, acc);

    float* C = Abuf + (size_t)bh * SEQ * SEQ;
    const int tid = threadIdx.x, lane = tid & 31, wid = tid >> 5;
    const int morg = (wid >> 2) * 64, norg = (wid & 3) * 32;
    const int* mb = mask + b * SEQ;
    float2* smst = (float2*)sm;

    #pragma unroll
    for (int mf = 0; mf < 4; mf++) {
        int rl0 = morg + mf * 16 + (lane >> 2);
        int rl1 = rl0 + 8;
        int r0 = tileM + rl0, r1 = tileM + rl1;
        int mr0 = mb[r0], mr1 = mb[r1];
        float tm0 = -1e38f, ts0 = 0.f, tm1 = -1e38f, ts1 = 0.f;
        #pragma unroll
        for (int j = 0; j < 4; j++) {
            int col = tileN + norg + j * 8 + (lane & 3) * 2;
            int mc0 = mb[col], mc1 = mb[col + 1];
            const float* ap0 = AP + (size_t)r0 * SEQ + col;
            const float* ap1 = AP + (size_t)r1 * SEQ + col;
            float2 o0, o1;
            o0.x = (mr0 && mc0) ? acc[mf][j][0] + ap0[0] : NEG_INF;
            o0.y = (mr0 && mc1) ? acc[mf][j][1] + ap0[1] : NEG_INF;
            o1.x = (mr1 && mc0) ? acc[mf][j][2] + ap1[0] : NEG_INF;
            o1.y = (mr1 && mc1) ? acc[mf][j][3] + ap1[1] : NEG_INF;
            *(float2*)(C + (size_t)r0 * SEQ + col) = o0;
            *(float2*)(C + (size_t)r1 * SEQ + col) = o1;
            float mx0 = fmaxf(tm0, fmaxf(o0.x, o0.y));
            ts0 = ts0 * __expf(tm0 - mx0) + __expf(o0.x - mx0) + __expf(o0.y - mx0);
            tm0 = mx0;
            float mx1 = fmaxf(tm1, fmaxf(o1.x, o1.y));
            ts1 = ts1 * __expf(tm1 - mx1) + __expf(o1.x - mx1) + __expf(o1.y - mx1);
            tm1 = mx1;
        }
        #pragma unroll
        for (int dx = 1; dx <= 2; dx <<= 1) {
            float om = __shfl_xor_sync(0xffffffff, tm0, dx);
            float os = __shfl_xor_sync(0xffffffff, ts0, dx);
            float M = fmaxf(tm0, om);
            ts0 = ts0 * __expf(tm0 - M) + os * __expf(om - M);
            tm0 = M;
            om = __shfl_xor_sync(0xffffffff, tm1, dx);
            os = __shfl_xor_sync(0xffffffff, ts1, dx);
            M = fmaxf(tm1, om);
            ts1 = ts1 * __expf(tm1 - M) + os * __expf(om - M);
            tm1 = M;
        }
        if ((lane & 3) == 0) {
            int base = wid * 64 + mf * 16 + (lane >> 2);
            smst[base]     = make_float2(tm0, ts0);
            smst[base + 8] = make_float2(tm1, ts1);
        }
    }
    __syncthreads();
    if (tid < 128) {
        int grp = tid >> 6;
        int rl = tid & 63;
        float M = -1e38f, S = 0.f;
        #pragma unroll
        for (int w = 0; w < 4; w++) {
            float2 p = smst[(grp * 4 + w) * 64 + rl];
            float Mn = fmaxf(M, p.x);
            S = S * __expf(M - Mn) + p.y * __expf(p.x - Mn);
            M = Mn;
        }
        part[((size_t)bh * SEQ + tileM + grp * 64 + rl) * 16 + blockIdx.x] = make_float2(M, S);
    }
}

// ===================== merge partial stats =====================
__global__ void __launch_bounds__(256) statsmerge_kernel(
    const float2* __restrict__ part, float2* __restrict__ stats)
{
    int row = blockIdx.x * blockDim.x + threadIdx.x;
    if (row >= BSZ * NHEADS * SEQ) return;
    const float2* p = part + (size_t)row * 16;
    float M = -1e38f, S = 0.f;
    #pragma unroll
    for (int t = 0; t < 16; t++) {
        float2 q = p[t];
        float Mn = fmaxf(M, q.x);
        S = S * __expf(M - Mn) + q.y * __expf(q.x - Mn);
        M = Mn;
    }
    stats[row] = make_float2(M, S);
}

// ===================== av =====================
#define TT_STAGE 34816
#define TT_SMEM (2 * TT_STAGE)

__device__ __forceinline__ float4 exp_norm4(float4 v, float mx, float inv) {
    v.x = __expf(v.x - mx) * inv;
    v.y = __expf(v.y - mx) * inv;
    v.z = __expf(v.z - mx) * inv;
    v.w = __expf(v.w - mx) * inv;
    return v;
}

__global__ void __launch_bounds__(256, 2) av_kernel(
    const float* __restrict__ V, const float* __restrict__ Abuf,
    const float2* __restrict__ stats,
    float* __restrict__ attOut, int hasAtt, float* __restrict__ Y)
{
    extern __shared__ char sm[];
    float acc[4][4][4] = {};
    const int bh = blockIdx.y;
    const int b = bh >> 3, h = bh & 7;
    const int tileM = blockIdx.x * 128;
    const float* Ag = Abuf + (size_t)bh * SEQ * SEQ + tileM;
    const float* Bg = V + (size_t)bh * SEQ * DH;
    const float2* strow = stats + (size_t)bh * SEQ;
    float* attB = attOut + (size_t)b * SEQ * SEQ + tileM;
    const bool wAtt = (h == 7) && hasAtt;

    const int tid = threadIdx.x, lane = tid & 31, wid = tid >> 5;
    const int morg = (wid >> 2) * 64, norg = (wid & 3) * 32;
    const int kr = tid >> 5, cg = tid & 31;
    const uint32_t sbase = smem_u32(sm);
    const int nc = SEQ / 32;
    float4 va[4], vb[4];

    #pragma unroll
    for (int rb = 0; rb < 4; rb++) {
        int j = kr + rb * 8;
        float2 st = strow[j];
        float inv = 1.0f / st.y;
        float4 v = *(const float4*)(Ag + (size_t)j * SEQ + cg * 4);
        v = exp_norm4(v, st.x, inv);
        if (wAtt) *(float4*)(attB + (size_t)j * SEQ + cg * 4) = v;
        va[rb] = v;
        vb[rb] = *(const float4*)(Bg + (size_t)j * DH + cg * 4);
    }
    {
        char* st = sm;
        #pragma unroll
        for (int rb = 0; rb < 4; rb++) {
            uint2 hi, lo;
            int off = (kr + rb * 8) * 272 + cg * 8;
            split4(va[rb], hi, lo);
            *(uint2*)(st + off) = hi; *(uint2*)(st + 8704 + off) = lo;
            split4(vb[rb], hi, lo);
            *(uint2*)(st + 17408 + off) = hi; *(uint2*)(st + 26112 + off) = lo;
        }
    }

    for (int c = 0; c < nc; c++) {
        __syncthreads();
        if (c + 1 < nc) {
            #pragma unroll
            for (int rb = 0; rb < 4; rb++) {
                int j = (c + 1) * 32 + kr + rb * 8;
                float2 st = strow[j];
                float inv = 1.0f / st.y;
                float4 v = *(const float4*)(Ag + (size_t)j * SEQ + cg * 4);
                v = exp_norm4(v, st.x, inv);
                if (wAtt) *(float4*)(attB + (size_t)j * SEQ + cg * 4) = v;
                va[rb] = v;
                vb[rb] = *(const float4*)(Bg + (size_t)j * DH + cg * 4);
            }
        }
        const uint32_t sst = sbase + (c & 1) * TT_STAGE;
        #pragma unroll
        for (int kh = 0; kh < 2; kh++) {
            uint32_t Ah[4][4], Al[4][4], Bh[2][4], Bl[2][4];
            #pragma unroll
            for (int mf = 0; mf < 4; mf++) {
                uint32_t krow = (lane & 7) + ((lane >> 4) << 3) + kh * 16;
                uint32_t ad = sst + krow * 272 + (((lane >> 3) & 1) << 4) + (morg + mf * 16) * 2;
                ldsm4_t(Ah[mf], ad);
                ldsm4_t(Al[mf], ad + 8704);
            }
            #pragma unroll
            for (int nb = 0; nb < 2; nb++) {
                uint32_t krow = (lane & 7) + (((lane >> 3) & 1) << 3) + kh * 16;
                uint32_t ad = sst + 17408 + krow * 272 + ((lane >> 4) << 4) + (norg + nb * 16) * 2;
                ldsm4_t(Bh[nb], ad);
                ldsm4_t(Bl[nb], ad + 8704);
            }
            #pragma unroll
            for (int mf = 0; mf < 4; mf++)
                #pragma unroll
                for (int j = 0; j < 4; j++) {
                    uint32_t b0h = Bh[j >> 1][(j & 1) * 2], b1h = Bh[j >> 1][(j & 1) * 2 + 1];
                    uint32_t b0l = Bl[j >> 1][(j & 1) * 2], b1l = Bl[j >> 1][(j & 1) * 2 + 1];
                    mma16816(acc[mf][j], Ah[mf], b0h, b1h);
                    mma16816(acc[mf][j], Ah[mf], b0l, b1l);
                    mma16816(acc[mf][j], Al[mf], b0h, b1h);
                }
        }
        __syncthreads();
        if (c + 1 < nc) {
            char* st = sm + ((c + 1) & 1) * TT_STAGE;
            #pragma unroll
            for (int rb = 0; rb < 4; rb++) {
                uint2 hi, lo;
                int off = (kr + rb * 8) * 272 + cg * 8;
                split4(va[rb], hi, lo);
                *(uint2*)(st + off) = hi; *(uint2*)(st + 8704 + off) = lo;
                split4(vb[rb], hi, lo);
                *(uint2*)(st + 17408 + off) = hi; *(uint2*)(st + 26112 + off) = lo;
            }
        }
    }

    #pragma unroll
    for (int mf = 0; mf < 4; mf++) {
        int i0 = tileM + (wid >> 2) * 64 + mf * 16 + (lane >> 2);
        #pragma unroll
        for (int j = 0; j < 4; j++) {
            int e = (wid & 3) * 32 + j * 8 + (lane & 3) * 2;
            float* d0 = Y + ((size_t)b * SEQ + i0) * DMODEL + h * DH + e;
            float* d1 = Y + ((size_t)b * SEQ + i0 + 8) * DMODEL + h * DH + e;
            *(float2*)d0 = make_float2(acc[mf][j][0], acc[mf][j][1]);
            *(float2*)d1 = make_float2(acc[mf][j][2], acc[mf][j][3]);
        }
    }
}

// ===================== out = Y * Wout^T (512 thr, 256x128 tile) ==========
__global__ void __launch_bounds__(512, 1) outproj_kernel(
    const float* __restrict__ Y, const float* __restrict__ Wout, float* __restrict__ out)
{
    extern __shared__ char sm[];
    float acc[4][4][4] = {};
    const int tileM = blockIdx.y * 256, tileN = blockIdx.x * 128;
    gemm_nt_mma_512(Y + (size_t)tileM * DMODEL, DMODEL,
                    Wout + (size_t)tileN * DMODEL, DMODEL, DMODEL, sm, acc);

    const int lane = threadIdx.x & 31, wid = threadIdx.x >> 5;
    #pragma unroll
    for (int mf = 0; mf < 4; mf++) {
        int row = tileM + (wid >> 2) * 64 + mf * 16 + (lane >> 2);
        #pragma unroll
        for (int j = 0; j < 4; j++) {
            int col = tileN + (wid & 3) * 32 + j * 8 + (lane & 3) * 2;
            *(float2*)(out + (size_t)row * DMODEL + col) =
                make_float2(acc[mf][j][0], acc[mf][j][1]);
            *(float2*)(out + (size_t)(row + 8) * DMODEL + col) =
                make_float2(acc[mf][j][2], acc[mf][j][3]);
        }
    }
}

// ===================== AP table =====================
__global__ void ap_kernel(float* __restrict__ AP) {
    int idx = blockIdx.x * blockDim.x + threadIdx.x;
    const int total = SEQ * (SEQ / 2);
    if (idx >= total) return;
    int p = idx / (SEQ / 2);
    int i = idx % (SEQ / 2);
    float denom = powf(10000.0f, (2.0f * (float)i) / 1024.0f);
    float angle = (float)p / denom;
    float s, c;
    sincosf(angle, &s, &c);
    AP[(size_t)p * SEQ + 2 * i]     = s;
    AP[(size_t)p * SEQ + 2 * i + 1] = c;
}

// ===================== launch =====================
extern "C" void kernel_launch(void* const* d_in, const int* in_sizes, int n_in,
                              void* d_out, int out_size) {
    const float* x    = (const float*)d_in[0];
    const int*   mask = (const int*)  d_in[1];
    const float* Wq   = (const float*)d_in[2];
    const float* Wk   = (const float*)d_in[3];
    const float* Wv   = (const float*)d_in[4];
    const float* Wout = (const float*)d_in[5];
    float* out = (float*)d_out;

    const long long outElems = (long long)BSZ * SEQ * DMODEL;
    const long long attElems = (long long)BSZ * SEQ * SEQ;
    int hasAtt = ((long long)out_size >= outElems + attElems) ? 1 : 0;
    float* attOut = out + outElems;

    float *Qp, *Kp, *Vp, *APp, *Ap, *Yp;
    float2 *Sp, *Pp;
    cudaGetSymbolAddress((void**)&Qp,  g_Q);
    cudaGetSymbolAddress((void**)&Kp,  g_K);
    cudaGetSymbolAddress((void**)&Vp,  g_V);
    cudaGetSymbolAddress((void**)&APp, g_AP);
    cudaGetSymbolAddress((void**)&Ap,  g_A);
    cudaGetSymbolAddress((void**)&Sp,  g_stats);
    cudaGetSymbolAddress((void**)&Pp,  g_part);
    cudaGetSymbolAddress((void**)&Yp,  g_Y);

    cudaFuncSetAttribute(qkv_kernel,     cudaFuncAttributeMaxDynamicSharedMemorySize, NT5_SMEM);
    cudaFuncSetAttribute(scores_kernel,  cudaFuncAttributeMaxDynamicSharedMemorySize, NT_SMEM);
    cudaFuncSetAttribute(outproj_kernel, cudaFuncAttributeMaxDynamicSharedMemorySize, NT5_SMEM);
    cudaFuncSetAttribute(av_kernel,      cudaFuncAttributeMaxDynamicSharedMemorySize, TT_SMEM);

    // 1. AP table
    {
        int total = SEQ * (SEQ / 2);
        ap_kernel<<<(total + 255) / 256, 256>>>(APp);
    }
    // 2. Q/K/V projections (512-thread 256x128 tiles, one launch)
    {
        dim3 g(DMODEL / 128, (BSZ * SEQ) / 256, 3);
        qkv_kernel<<<g, 512, NT5_SMEM>>>(x, Wq, Wk, Wv, Qp, Kp, Vp);
    }
    // 3. scores -> g_A + per-tile row stats
    {
        dim3 g(SEQ / 128, SEQ / 128, BSZ * NHEADS);
        scores_kernel<<<g, 256, NT_SMEM>>>(Qp, Kp, mask, APp, Ap, Pp);
    }
    // 4. merge partial stats
    statsmerge_kernel<<<(BSZ * NHEADS * SEQ + 255) / 256, 256>>>(Pp, Sp);
    // 5. y = A^T V with softmax at load (+ attOut for h==7)
    {
        dim3 g(SEQ / 128, BSZ * NHEADS);
        av_kernel<<<g, 256, TT_SMEM>>>(Vp, Ap, Sp, attOut, hasAtt, Yp);
    }
    // 6. out projection (512-thread 256x128 tiles)
    {
        dim3 g(DMODEL / 128, (BSZ * SEQ) / 256);
        outproj_kernel<<<g, 512, NT5_SMEM>>>(Yp, Wout, out);
    }
}